// round 7
// baseline (speedup 1.0000x reference)
#include <cuda_runtime.h>
#include <math.h>

// Problem constants
constexpr int B  = 2;
constexpr int S  = 2048;
constexpr int D  = 1024;
constexpr int H  = 16;
constexpr int HD = 64;
constexpr int BS = B * S;          // 4096 rows
constexpr int N_QKV = 3 * D;       // 3072

// Scratch (device globals — no allocation allowed)
__device__ float g_Q[B * H * S * HD];     // [b,h,s,hd]   (tf32-pre-rounded)
__device__ float g_K[B * H * S * HD];     //              (tf32-pre-rounded)
__device__ float g_V[B * H * S * HD];     //              (tf32-pre-rounded)
__device__ float g_attn[BS * D];          // [b,s,d]      (tf32-pre-rounded)
__device__ float g_xr[BS * D];            // x rounded to tf32
__device__ float g_wqkv[N_QKV * D];       // qkv_w rounded to tf32
__device__ float g_wout[D * D];           // out_w rounded to tf32

// ---------------------------------------------------------------------------
// Helpers
// ---------------------------------------------------------------------------
__device__ __forceinline__ unsigned f2tf32(float f) {
    unsigned u;
    asm("cvt.rna.tf32.f32 %0, %1;" : "=r"(u) : "f"(f));
    return u;
}
__device__ __forceinline__ float rnd_tf32(float f) {
    return __uint_as_float(f2tf32(f));
}
__device__ __forceinline__ unsigned smem_u32(const void* p) {
    unsigned a;
    asm("{ .reg .u64 t; cvta.to.shared.u64 t, %1; cvt.u32.u64 %0, t; }"
        : "=r"(a) : "l"(p));
    return a;
}
#define CP_ASYNC16(dst, src) \
    asm volatile("cp.async.cg.shared.global [%0], [%1], 16;" :: "r"(dst), "l"(src))
#define CP_COMMIT() asm volatile("cp.async.commit_group;")

// D += A * B  (m16n8k8, A row-major, B col-major, tf32 in, fp32 accum)
__device__ __forceinline__ void mma8(float& d0, float& d1, float& d2, float& d3,
                                     unsigned a0, unsigned a1, unsigned a2, unsigned a3,
                                     unsigned b0, unsigned b1) {
    asm volatile(
        "mma.sync.aligned.m16n8k8.row.col.f32.tf32.tf32.f32 "
        "{%0,%1,%2,%3}, {%4,%5,%6,%7}, {%8,%9}, {%0,%1,%2,%3};"
        : "+f"(d0), "+f"(d1), "+f"(d2), "+f"(d3)
        : "r"(a0), "r"(a1), "r"(a2), "r"(a3), "r"(b0), "r"(b1));
}

// ---------------------------------------------------------------------------
// Pre-round pass: x, qkv_w, out_w -> tf32 (rna) copies, so GEMMs can cp.async
// raw bits with numerics identical to explicit conversion.
// ---------------------------------------------------------------------------
__global__ __launch_bounds__(256) void round_pre(
    const float* __restrict__ x,
    const float* __restrict__ wqkv,
    const float* __restrict__ wout)
{
    const int NX = BS * D / 4, NW = N_QKV * D / 4, NO = D * D / 4;
    const int total = NX + NW + NO;
    for (int idx = blockIdx.x * blockDim.x + threadIdx.x; idx < total;
         idx += gridDim.x * blockDim.x) {
        const float4* src;
        float4* dst;
        int off;
        if (idx < NX)            { src = (const float4*)x;    dst = (float4*)g_xr;   off = idx; }
        else if (idx < NX + NW)  { src = (const float4*)wqkv; dst = (float4*)g_wqkv; off = idx - NX; }
        else                     { src = (const float4*)wout; dst = (float4*)g_wout; off = idx - NX - NW; }
        float4 v = src[off];
        v.x = rnd_tf32(v.x); v.y = rnd_tf32(v.y);
        v.z = rnd_tf32(v.z); v.w = rnd_tf32(v.w);
        dst[off] = v;
    }
}

// ---------------------------------------------------------------------------
// TF32 tensor-core GEMM with 3-stage cp.async pipeline (single barrier/chunk).
// C[m,n] = sum_k A[m,k] * W[n,k] + bias[n]
// BM=BN=128, BK=32, 256 threads = 8 warps (4 M x 2 N), warp tile 32x64.
// A/W are pre-rounded device globals. SCATTER=true -> Q/K/V head-major scatter
// (values re-rounded to tf32); SCATTER=false -> plain fp32 store to C.
// Dynamic smem: 3 * 2 * 128*36 * 4 = 110592 bytes.
// ---------------------------------------------------------------------------
template <bool SCATTER>
__global__ __launch_bounds__(256) void gemm_mma(
    const float* __restrict__ bias,
    float* __restrict__ C)
{
    constexpr int AST = 36, TILE = 128 * AST;
    extern __shared__ unsigned smg[];
    unsigned* As = smg;               // [3][TILE]
    unsigned* Bs = smg + 3 * TILE;    // [3][TILE]
    const unsigned sA = smem_u32(As);
    const unsigned sB = smem_u32(Bs);

    const float* Ap = SCATTER ? g_xr   : g_attn;
    const float* Wp = SCATTER ? g_wqkv : g_wout;

    const int t    = threadIdx.x;
    const int lane = t & 31;
    const int w    = t >> 5;
    const int g    = lane >> 2;     // 0..7
    const int tig  = lane & 3;      // 0..3
    const int wm   = w & 3;         // 0..3
    const int wn   = w >> 2;        // 0..1
    const int m0   = blockIdx.y * 128;
    const int n0   = blockIdx.x * 128;

    float acc[2][8][4];
    #pragma unroll
    for (int tm = 0; tm < 2; tm++)
        #pragma unroll
        for (int nt = 0; nt < 8; nt++)
            #pragma unroll
            for (int q = 0; q < 4; q++) acc[tm][nt][q] = 0.f;

    // Per-thread copy map: 4 x 16B per tile per stage
    const int id_row[4] = { (t + 0)   >> 3, (t + 256) >> 3,
                            (t + 512) >> 3, (t + 768) >> 3 };
    const int id_c4 = (t & 7) * 4;

    auto issue = [&](int k0, int buf) {
        #pragma unroll
        for (int r = 0; r < 4; r++) {
            const int row = id_row[r];
            const unsigned soff = (unsigned)(buf * TILE + row * AST + id_c4) * 4u;
            CP_ASYNC16(sA + soff, &Ap[(size_t)(m0 + row) * D + k0 + id_c4]);
            CP_ASYNC16(sB + soff, &Wp[(size_t)(n0 + row) * D + k0 + id_c4]);
        }
        CP_COMMIT();
    };

    constexpr int NK = D / 32;      // 32 k-chunks
    issue(0, 0);
    issue(32, 1);
    for (int i = 0; i < NK; i++) {
        if (i < NK - 1) asm volatile("cp.async.wait_group 1;");
        else            asm volatile("cp.async.wait_group 0;");
        __syncthreads();
        // Issue into buf (i+2)%3 == buf (i-1)%3: everyone is provably past
        // reading it (the barrier above follows compute of chunk i-1).
        if (i + 2 < NK) issue((i + 2) * 32, (i + 2) % 3);

        const unsigned* Ab = As + (i % 3) * TILE;
        const unsigned* Bb = Bs + (i % 3) * TILE;
        #pragma unroll
        for (int ks = 0; ks < 4; ks++) {
            unsigned af[2][4];
            #pragma unroll
            for (int tm = 0; tm < 2; tm++) {
                const int rb = (wm * 32 + tm * 16) * AST + ks * 8;
                af[tm][0] = Ab[rb + g * AST + tig];
                af[tm][1] = Ab[rb + (g + 8) * AST + tig];
                af[tm][2] = Ab[rb + g * AST + tig + 4];
                af[tm][3] = Ab[rb + (g + 8) * AST + tig + 4];
            }
            unsigned bf[8][2];
            #pragma unroll
            for (int nt = 0; nt < 8; nt++) {
                const int rb = (wn * 64 + nt * 8 + g) * AST + ks * 8;
                bf[nt][0] = Bb[rb + tig];
                bf[nt][1] = Bb[rb + tig + 4];
            }
            #pragma unroll
            for (int tm = 0; tm < 2; tm++)
                #pragma unroll
                for (int nt = 0; nt < 8; nt++)
                    mma8(acc[tm][nt][0], acc[tm][nt][1], acc[tm][nt][2], acc[tm][nt][3],
                         af[tm][0], af[tm][1], af[tm][2], af[tm][3],
                         bf[nt][0], bf[nt][1]);
        }
    }

    // Epilogue: C frag rows (g, g+8), cols (2tig, 2tig+1)
    #pragma unroll
    for (int tm = 0; tm < 2; tm++) {
        const int r0 = m0 + wm * 32 + tm * 16 + g;
        #pragma unroll
        for (int nt = 0; nt < 8; nt++) {
            const int c = n0 + wn * 64 + nt * 8 + 2 * tig;
            const float b0 = bias[c], b1 = bias[c + 1];
            float2 v0 = { acc[tm][nt][0] + b0, acc[tm][nt][1] + b1 };
            float2 v1 = { acc[tm][nt][2] + b0, acc[tm][nt][3] + b1 };
            if (SCATTER) {
                v0.x = rnd_tf32(v0.x); v0.y = rnd_tf32(v0.y);
                v1.x = rnd_tf32(v1.x); v1.y = rnd_tf32(v1.y);
                const int which = c >> 10;          // 0=Q,1=K,2=V
                const int dd = c & (D - 1);
                const int h  = dd >> 6;
                const int hi = dd & (HD - 1);       // even
                float* dst = (which == 0) ? g_Q : (which == 1) ? g_K : g_V;
                const int bb0 = r0 >> 11, ss0 = r0 & (S - 1);
                const int bb1 = (r0 + 8) >> 11, ss1 = (r0 + 8) & (S - 1);
                *(float2*)&dst[(((size_t)(bb0 * H + h) * S) + ss0) * HD + hi] = v0;
                *(float2*)&dst[(((size_t)(bb1 * H + h) * S) + ss1) * HD + hi] = v1;
            } else {
                *(float2*)&C[(size_t)r0 * D + c] = v0;
                *(float2*)&C[(size_t)(r0 + 8) * D + c] = v1;
            }
        }
    }
}

// ---------------------------------------------------------------------------
// TF32 tensor-core attention (quirk: scores[i,j] = k_i . q_j, scale 1/8),
// 3-stage cp.async pipeline for the 64-row Q/V j-tiles, one barrier per tile.
// CTA: 128 i-rows (K side), 8 warps x 16 rows.
// No max subtraction (scores are tiny): l += e^{s/8}, O += e^{s/8} V.
// Dynamic smem: 3 stages * (Q+V) * 64*68 * 4 = 104448 bytes.
// ---------------------------------------------------------------------------
__global__ __launch_bounds__(256) void flash_attn_mma()
{
    constexpr int QST = 68, QTILE = 64 * QST;
    extern __shared__ unsigned smg[];
    unsigned* Qs = smg;               // [3][QTILE]
    unsigned* Vs = smg + 3 * QTILE;   // [3][QTILE]
    __shared__ unsigned Ps[2][128 * 12];
    const unsigned sQ = smem_u32(Qs);
    const unsigned sV = smem_u32(Vs);

    const int bh = blockIdx.x;                 // b*H + h
    const int i0 = blockIdx.y * 128;
    const int t    = threadIdx.x;
    const int lane = t & 31;
    const int w    = t >> 5;
    const int g    = lane >> 2;
    const int tig  = lane & 3;

    const float* Kp = g_K + (size_t)bh * S * HD;
    const float* Qp = g_Q + (size_t)bh * S * HD;
    const float* Vp = g_V + (size_t)bh * S * HD;

    // K A-fragments (g_K is tf32-pre-rounded: raw bits are the tf32 operands)
    unsigned ak[8][4];
    {
        const int kr = i0 + w * 16 + g;
        #pragma unroll
        for (int ks = 0; ks < 8; ks++) {
            ak[ks][0] = __float_as_uint(Kp[(size_t)kr * HD + ks * 8 + tig]);
            ak[ks][1] = __float_as_uint(Kp[(size_t)(kr + 8) * HD + ks * 8 + tig]);
            ak[ks][2] = __float_as_uint(Kp[(size_t)kr * HD + ks * 8 + tig + 4]);
            ak[ks][3] = __float_as_uint(Kp[(size_t)(kr + 8) * HD + ks * 8 + tig + 4]);
        }
    }

    float o[8][4];
    #pragma unroll
    for (int dt = 0; dt < 8; dt++)
        #pragma unroll
        for (int q = 0; q < 4; q++) o[dt][q] = 0.f;
    float l0 = 0.f, l1 = 0.f;
    const float C1 = 0.18033688011112042f;     // log2(e)/8

    const int jrow = t >> 2;                   // copy map: 0..63
    const int jc4  = (t & 3) * 4;              // covers 16 of 64 cols
    auto issue = [&](int j0, int buf) {
        #pragma unroll
        for (int r = 0; r < 4; r++) {
            const int c4 = jc4 + r * 16;
            const unsigned soff = (unsigned)(buf * QTILE + jrow * QST + c4) * 4u;
            CP_ASYNC16(sQ + soff, &Qp[(size_t)(j0 + jrow) * HD + c4]);
            CP_ASYNC16(sV + soff, &Vp[(size_t)(j0 + jrow) * HD + c4]);
        }
        CP_COMMIT();
    };

    constexpr int NJ = S / 64;   // 32 tiles
    issue(0, 0);
    issue(64, 1);
    for (int i = 0; i < NJ; i++) {
        if (i < NJ - 1) asm volatile("cp.async.wait_group 1;");
        else            asm volatile("cp.async.wait_group 0;");
        __syncthreads();
        if (i + 2 < NJ) issue((i + 2) * 64, (i + 2) % 3);

        const unsigned* Qb = Qs + (i % 3) * QTILE;
        const unsigned* Vb = Vs + (i % 3) * QTILE;

        #pragma unroll
        for (int nt = 0; nt < 8; nt++) {
            // --- mma1: S chunk = K(16 rows) x Q(8 j's) over hd=64
            float c0 = 0.f, c1 = 0.f, c2 = 0.f, c3 = 0.f;
            const int qr = (nt * 8 + g) * QST;
            #pragma unroll
            for (int ks = 0; ks < 8; ks++) {
                unsigned b0 = Qb[qr + ks * 8 + tig];
                unsigned b1 = Qb[qr + ks * 8 + tig + 4];
                mma8(c0, c1, c2, c3, ak[ks][0], ak[ks][1], ak[ks][2], ak[ks][3], b0, b1);
            }
            // --- softmax numerator (no max-sub; scores are small)
            float p0 = exp2f(c0 * C1);
            float p1 = exp2f(c1 * C1);
            float p2 = exp2f(c2 * C1);
            float p3 = exp2f(c3 * C1);
            l0 += p0 + p1;
            l1 += p2 + p3;
            // --- re-fragment P via smem (per-warp private rows)
            unsigned* pb = &Ps[nt & 1][0];
            uint2 u0 = { f2tf32(p0), f2tf32(p1) };
            uint2 u1 = { f2tf32(p2), f2tf32(p3) };
            *(uint2*)&pb[(w * 16 + g) * 12 + 2 * tig] = u0;
            *(uint2*)&pb[(w * 16 + g + 8) * 12 + 2 * tig] = u1;
            __syncwarp();
            unsigned a0 = pb[(w * 16 + g) * 12 + tig];
            unsigned a1 = pb[(w * 16 + g + 8) * 12 + tig];
            unsigned a2 = pb[(w * 16 + g) * 12 + tig + 4];
            unsigned a3 = pb[(w * 16 + g + 8) * 12 + tig + 4];
            // --- mma2: O += P(16x8) x V(8 j's x 64 d)
            const int vr0 = (nt * 8 + tig) * QST;
            const int vr1 = (nt * 8 + tig + 4) * QST;
            #pragma unroll
            for (int dt = 0; dt < 8; dt++) {
                unsigned b0 = Vb[vr0 + dt * 8 + g];
                unsigned b1 = Vb[vr1 + dt * 8 + g];
                mma8(o[dt][0], o[dt][1], o[dt][2], o[dt][3], a0, a1, a2, a3, b0, b1);
            }
        }
    }

    // Reduce l across the 4 lanes sharing a row, normalize, write out
    l0 += __shfl_xor_sync(0xffffffff, l0, 1);
    l0 += __shfl_xor_sync(0xffffffff, l0, 2);
    l1 += __shfl_xor_sync(0xffffffff, l1, 1);
    l1 += __shfl_xor_sync(0xffffffff, l1, 2);
    const float inv0 = 1.f / l0;
    const float inv1 = 1.f / l1;

    const int bb = bh >> 4;
    const int h  = bh & (H - 1);
    const int r0 = i0 + w * 16 + g;
    float* d0 = g_attn + ((size_t)(bb * S + r0)) * D + h * HD;
    float* d1 = g_attn + ((size_t)(bb * S + r0 + 8)) * D + h * HD;
    #pragma unroll
    for (int dt = 0; dt < 8; dt++) {
        float2 v0 = { rnd_tf32(o[dt][0] * inv0), rnd_tf32(o[dt][1] * inv0) };
        float2 v1 = { rnd_tf32(o[dt][2] * inv1), rnd_tf32(o[dt][3] * inv1) };
        *(float2*)&d0[dt * 8 + 2 * tig] = v0;
        *(float2*)&d1[dt * 8 + 2 * tig] = v1;
    }
}

// ---------------------------------------------------------------------------
extern "C" void kernel_launch(void* const* d_in, const int* in_sizes, int n_in,
                              void* d_out, int out_size)
{
    const float* x     = (const float*)d_in[0];
    const float* qkv_w = (const float*)d_in[1];
    const float* qkv_b = (const float*)d_in[2];
    const float* out_w = (const float*)d_in[3];
    const float* out_b = (const float*)d_in[4];
    float* out = (float*)d_out;

    constexpr int GEMM_SMEM = 3 * 2 * 128 * 36 * 4;   // 110592
    constexpr int ATTN_SMEM = 3 * 2 * 64 * 68 * 4;    // 104448
    cudaFuncSetAttribute(gemm_mma<true>,  cudaFuncAttributeMaxDynamicSharedMemorySize, GEMM_SMEM);
    cudaFuncSetAttribute(gemm_mma<false>, cudaFuncAttributeMaxDynamicSharedMemorySize, GEMM_SMEM);
    cudaFuncSetAttribute(flash_attn_mma,  cudaFuncAttributeMaxDynamicSharedMemorySize, ATTN_SMEM);

    // 0) Pre-round x and weights to tf32 so GEMMs can cp.async raw bits
    round_pre<<<2048, 256>>>(x, qkv_w, out_w);

    // 1) QKV projection (tf32 mma, cp.async pipeline), scatter to Q/K/V
    gemm_mma<true><<<dim3(N_QKV / 128, BS / 128), 256, GEMM_SMEM>>>(qkv_b, nullptr);

    // 2) Attention (quirk: K is the query side), tf32 mma + cp.async pipeline
    flash_attn_mma<<<dim3(B * H, S / 128), 256, ATTN_SMEM>>>();

    // 3) Output projection
    gemm_mma<false><<<dim3(D / 128, BS / 128), 256, GEMM_SMEM>>>(out_b, out);
}

// round 9
// speedup vs baseline: 1.1836x; 1.1836x over previous
#include <cuda_runtime.h>
#include <math.h>

// Problem constants
constexpr int B  = 2;
constexpr int S  = 2048;
constexpr int D  = 1024;
constexpr int H  = 16;
constexpr int HD = 64;
constexpr int BS = B * S;          // 4096 rows
constexpr int N_QKV = 3 * D;       // 3072

// Scratch (device globals — no allocation allowed)
__device__ float g_Q[B * H * S * HD];     // [b,h,s,hd]   (tf32-pre-rounded)
__device__ float g_K[B * H * S * HD];     //              (tf32-pre-rounded)
__device__ float g_V[B * H * S * HD];     //              (tf32-pre-rounded)
__device__ float g_attn[BS * D];          // [b,s,d]      (tf32-pre-rounded)
__device__ float g_xr[BS * D];            // x rounded to tf32
__device__ float g_wqkv[N_QKV * D];       // qkv_w rounded to tf32
__device__ float g_wout[D * D];           // out_w rounded to tf32

// ---------------------------------------------------------------------------
// Helpers
// ---------------------------------------------------------------------------
__device__ __forceinline__ unsigned f2tf32(float f) {
    unsigned u;
    asm("cvt.rna.tf32.f32 %0, %1;" : "=r"(u) : "f"(f));
    return u;
}
__device__ __forceinline__ float rnd_tf32(float f) {
    return __uint_as_float(f2tf32(f));
}
__device__ __forceinline__ unsigned smem_u32(const void* p) {
    unsigned a;
    asm("{ .reg .u64 t; cvta.to.shared.u64 t, %1; cvt.u32.u64 %0, t; }"
        : "=r"(a) : "l"(p));
    return a;
}
#define CP_ASYNC16(dst, src) \
    asm volatile("cp.async.cg.shared.global [%0], [%1], 16;" :: "r"(dst), "l"(src))
#define CP_COMMIT() asm volatile("cp.async.commit_group;")

// ldmatrix x4: each lane supplies the smem address of one 16B row.
__device__ __forceinline__ void ldsm4(unsigned& d0, unsigned& d1,
                                      unsigned& d2, unsigned& d3, unsigned addr) {
    asm volatile("ldmatrix.sync.aligned.m8n8.x4.shared.b16 {%0,%1,%2,%3}, [%4];"
        : "=r"(d0), "=r"(d1), "=r"(d2), "=r"(d3) : "r"(addr));
}

// D += A * B  (m16n8k8, A row-major, B col-major, tf32 in, fp32 accum)
__device__ __forceinline__ void mma8(float& d0, float& d1, float& d2, float& d3,
                                     unsigned a0, unsigned a1, unsigned a2, unsigned a3,
                                     unsigned b0, unsigned b1) {
    asm volatile(
        "mma.sync.aligned.m16n8k8.row.col.f32.tf32.tf32.f32 "
        "{%0,%1,%2,%3}, {%4,%5,%6,%7}, {%8,%9}, {%0,%1,%2,%3};"
        : "+f"(d0), "+f"(d1), "+f"(d2), "+f"(d3)
        : "r"(a0), "r"(a1), "r"(a2), "r"(a3), "r"(b0), "r"(b1));
}

// ---------------------------------------------------------------------------
// Pre-round pass: x, qkv_w, out_w -> tf32 (rna) copies, so GEMMs can cp.async
// raw bits with numerics identical to explicit conversion.
// ---------------------------------------------------------------------------
__global__ __launch_bounds__(256) void round_pre(
    const float* __restrict__ x,
    const float* __restrict__ wqkv,
    const float* __restrict__ wout)
{
    const int NX = BS * D / 4, NW = N_QKV * D / 4, NO = D * D / 4;
    const int total = NX + NW + NO;
    for (int idx = blockIdx.x * blockDim.x + threadIdx.x; idx < total;
         idx += gridDim.x * blockDim.x) {
        const float4* src;
        float4* dst;
        int off;
        if (idx < NX)            { src = (const float4*)x;    dst = (float4*)g_xr;   off = idx; }
        else if (idx < NX + NW)  { src = (const float4*)wqkv; dst = (float4*)g_wqkv; off = idx - NX; }
        else                     { src = (const float4*)wout; dst = (float4*)g_wout; off = idx - NX - NW; }
        float4 v = src[off];
        v.x = rnd_tf32(v.x); v.y = rnd_tf32(v.y);
        v.z = rnd_tf32(v.z); v.w = rnd_tf32(v.w);
        dst[off] = v;
    }
}

// ---------------------------------------------------------------------------
// TF32 tensor-core GEMM, 2-stage cp.async pipeline, ldmatrix fragment loads.
// C[m,n] = sum_k A[m,k] * W[n,k] + bias[n]
// BM=BN=128, BK=32, 256 threads = 8 warps (4 M x 2 N), warp tile 32x64.
// Dynamic smem: 2 * 2 * 128*36 * 4 = 73728 bytes.
// ---------------------------------------------------------------------------
template <bool SCATTER>
__global__ __launch_bounds__(256) void gemm_mma(
    const float* __restrict__ bias,
    float* __restrict__ C)
{
    constexpr int AST = 36, TILE = 128 * AST;
    extern __shared__ unsigned smg[];
    unsigned* As = smg;               // [2][TILE]
    unsigned* Bs = smg + 2 * TILE;    // [2][TILE]
    const unsigned sA = smem_u32(As);
    const unsigned sB = smem_u32(Bs);

    const float* Ap = SCATTER ? g_xr   : g_attn;
    const float* Wp = SCATTER ? g_wqkv : g_wout;

    const int t    = threadIdx.x;
    const int lane = t & 31;
    const int w    = t >> 5;
    const int g    = lane >> 2;     // 0..7
    const int tig  = lane & 3;      // 0..3
    const int wm   = w & 3;         // 0..3
    const int wn   = w >> 2;        // 0..1
    const int m0   = blockIdx.y * 128;
    const int n0   = blockIdx.x * 128;

    // LDSM per-lane row/col map (element units within a tile)
    // A x4: m0: rows +0..7 @k+0 | m1: rows +8..15 @k+0 | m2: rows 0..7 @k+4 | m3: rows 8..15 @k+4
    const int a_row = wm * 32 + ((lane >> 3) & 1) * 8 + (lane & 7);
    const int a_col = (lane >> 4) * 4;
    const unsigned aoff = (unsigned)(a_row * AST + a_col) * 4u;
    // B x4 (two n-tiles): m0: rows nt*8+0..7 @k+0 | m1: same @k+4 | m2: rows (nt+1)*8.. @k+0 | m3: @k+4
    const int b_row = wn * 64 + ((lane >> 4) & 1) * 8 + (lane & 7);
    const int b_col = ((lane >> 3) & 1) * 4;
    const unsigned boff = (unsigned)(b_row * AST + b_col) * 4u;

    float acc[2][8][4];
    #pragma unroll
    for (int tm = 0; tm < 2; tm++)
        #pragma unroll
        for (int nt = 0; nt < 8; nt++)
            #pragma unroll
            for (int q = 0; q < 4; q++) acc[tm][nt][q] = 0.f;

    // Per-thread copy map: 4 x 16B per tile per stage
    const int id_row[4] = { (t + 0)   >> 3, (t + 256) >> 3,
                            (t + 512) >> 3, (t + 768) >> 3 };
    const int id_c4 = (t & 7) * 4;

    auto issue = [&](int k0, int buf) {
        #pragma unroll
        for (int r = 0; r < 4; r++) {
            const int row = id_row[r];
            const unsigned soff = (unsigned)(buf * TILE + row * AST + id_c4) * 4u;
            CP_ASYNC16(sA + soff, &Ap[(size_t)(m0 + row) * D + k0 + id_c4]);
            CP_ASYNC16(sB + soff, &Wp[(size_t)(n0 + row) * D + k0 + id_c4]);
        }
        CP_COMMIT();
    };

    constexpr int NK = D / 32;      // 32 k-chunks
    issue(0, 0);
    for (int i = 0; i < NK; i++) {
        if (i + 1 < NK) {
            issue((i + 1) * 32, (i + 1) & 1);
            asm volatile("cp.async.wait_group 1;");
        } else {
            asm volatile("cp.async.wait_group 0;");
        }
        __syncthreads();

        const unsigned Ab = sA + (unsigned)((i & 1) * TILE) * 4u;
        const unsigned Bb = sB + (unsigned)((i & 1) * TILE) * 4u;
        #pragma unroll
        for (int ks = 0; ks < 4; ks++) {
            unsigned af[2][4];
            ldsm4(af[0][0], af[0][1], af[0][2], af[0][3], Ab + aoff + ks * 32u);
            ldsm4(af[1][0], af[1][1], af[1][2], af[1][3],
                  Ab + aoff + 16u * AST * 4u + ks * 32u);
            unsigned bf[8][2];
            #pragma unroll
            for (int np = 0; np < 4; np++) {
                unsigned d0, d1, d2, d3;
                ldsm4(d0, d1, d2, d3, Bb + boff + (unsigned)(np * 16 * AST) * 4u + ks * 32u);
                bf[np * 2][0] = d0; bf[np * 2][1] = d1;
                bf[np * 2 + 1][0] = d2; bf[np * 2 + 1][1] = d3;
            }
            #pragma unroll
            for (int tm = 0; tm < 2; tm++)
                #pragma unroll
                for (int nt = 0; nt < 8; nt++)
                    mma8(acc[tm][nt][0], acc[tm][nt][1], acc[tm][nt][2], acc[tm][nt][3],
                         af[tm][0], af[tm][1], af[tm][2], af[tm][3],
                         bf[nt][0], bf[nt][1]);
        }
        __syncthreads();
    }

    // Epilogue: C frag rows (g, g+8), cols (2tig, 2tig+1)
    #pragma unroll
    for (int tm = 0; tm < 2; tm++) {
        const int r0 = m0 + wm * 32 + tm * 16 + g;
        #pragma unroll
        for (int nt = 0; nt < 8; nt++) {
            const int c = n0 + wn * 64 + nt * 8 + 2 * tig;
            const float b0 = bias[c], b1 = bias[c + 1];
            float2 v0 = { acc[tm][nt][0] + b0, acc[tm][nt][1] + b1 };
            float2 v1 = { acc[tm][nt][2] + b0, acc[tm][nt][3] + b1 };
            if (SCATTER) {
                v0.x = rnd_tf32(v0.x); v0.y = rnd_tf32(v0.y);
                v1.x = rnd_tf32(v1.x); v1.y = rnd_tf32(v1.y);
                const int which = c >> 10;          // 0=Q,1=K,2=V
                const int dd = c & (D - 1);
                const int h  = dd >> 6;
                const int hi = dd & (HD - 1);       // even
                float* dst = (which == 0) ? g_Q : (which == 1) ? g_K : g_V;
                const int bb0 = r0 >> 11, ss0 = r0 & (S - 1);
                const int bb1 = (r0 + 8) >> 11, ss1 = (r0 + 8) & (S - 1);
                *(float2*)&dst[(((size_t)(bb0 * H + h) * S) + ss0) * HD + hi] = v0;
                *(float2*)&dst[(((size_t)(bb1 * H + h) * S) + ss1) * HD + hi] = v1;
            } else {
                *(float2*)&C[(size_t)r0 * D + c] = v0;
                *(float2*)&C[(size_t)(r0 + 8) * D + c] = v1;
            }
        }
    }
}

// ---------------------------------------------------------------------------
// TF32 tensor-core attention (quirk: scores[i,j] = k_i . q_j, scale 1/8),
// 2-stage cp.async pipeline, ldmatrix Q-fragment loads.
// CTA: 128 i-rows (K side), 8 warps x 16 rows.
// No max subtraction (scores are tiny): l += e^{s/8}, O += e^{s/8} V.
// Dynamic smem: 2 stages * (Q+V) * 64*68 * 4 = 69632 bytes.
// ---------------------------------------------------------------------------
__global__ __launch_bounds__(256) void flash_attn_mma()
{
    constexpr int QST = 68, QTILE = 64 * QST;
    extern __shared__ unsigned smg[];
    unsigned* Qs = smg;               // [2][QTILE]
    unsigned* Vs = smg + 2 * QTILE;   // [2][QTILE]
    __shared__ unsigned Ps[2][128 * 12];
    const unsigned sQ = smem_u32(Qs);
    const unsigned sV = smem_u32(Vs);

    const int bh = blockIdx.x;                 // b*H + h
    const int i0 = blockIdx.y * 128;
    const int t    = threadIdx.x;
    const int lane = t & 31;
    const int w    = t >> 5;
    const int g    = lane >> 2;
    const int tig  = lane & 3;

    const float* Kp = g_K + (size_t)bh * S * HD;
    const float* Qp = g_Q + (size_t)bh * S * HD;
    const float* Vp = g_V + (size_t)bh * S * HD;

    // Q LDSM map: per nt, x4 over 16 k: m0 rows nt*8+0..7 @k+0, m1 @+4, m2 @+8, m3 @+12
    const unsigned qoff = (unsigned)((lane & 7) * QST + (lane >> 3) * 4) * 4u;

    // K A-fragments (g_K is tf32-pre-rounded: raw bits are the tf32 operands)
    unsigned ak[8][4];
    {
        const int kr = i0 + w * 16 + g;
        #pragma unroll
        for (int ks = 0; ks < 8; ks++) {
            ak[ks][0] = __float_as_uint(Kp[(size_t)kr * HD + ks * 8 + tig]);
            ak[ks][1] = __float_as_uint(Kp[(size_t)(kr + 8) * HD + ks * 8 + tig]);
            ak[ks][2] = __float_as_uint(Kp[(size_t)kr * HD + ks * 8 + tig + 4]);
            ak[ks][3] = __float_as_uint(Kp[(size_t)(kr + 8) * HD + ks * 8 + tig + 4]);
        }
    }

    float o[8][4];
    #pragma unroll
    for (int dt = 0; dt < 8; dt++)
        #pragma unroll
        for (int q = 0; q < 4; q++) o[dt][q] = 0.f;
    float l0 = 0.f, l1 = 0.f;
    const float C1 = 0.18033688011112042f;     // log2(e)/8

    const int jrow = t >> 2;                   // copy map: 0..63
    const int jc4  = (t & 3) * 4;              // covers 16 of 64 cols
    auto issue = [&](int j0, int buf) {
        #pragma unroll
        for (int r = 0; r < 4; r++) {
            const int c4 = jc4 + r * 16;
            const unsigned soff = (unsigned)(buf * QTILE + jrow * QST + c4) * 4u;
            CP_ASYNC16(sQ + soff, &Qp[(size_t)(j0 + jrow) * HD + c4]);
            CP_ASYNC16(sV + soff, &Vp[(size_t)(j0 + jrow) * HD + c4]);
        }
        CP_COMMIT();
    };

    constexpr int NJ = S / 64;   // 32 tiles
    issue(0, 0);
    for (int i = 0; i < NJ; i++) {
        if (i + 1 < NJ) {
            issue((i + 1) * 64, (i + 1) & 1);
            asm volatile("cp.async.wait_group 1;");
        } else {
            asm volatile("cp.async.wait_group 0;");
        }
        __syncthreads();

        const unsigned Qbb = sQ + (unsigned)((i & 1) * QTILE) * 4u;
        const unsigned* Vb = Vs + (i & 1) * QTILE;

        #pragma unroll
        for (int nt = 0; nt < 8; nt++) {
            // --- Q fragments via ldmatrix: 4 x ldsm4 cover ks=0..7
            unsigned qf[8][2];
            #pragma unroll
            for (int kb = 0; kb < 4; kb++) {
                unsigned d0, d1, d2, d3;
                ldsm4(d0, d1, d2, d3,
                      Qbb + qoff + (unsigned)(nt * 8 * QST) * 4u + (unsigned)kb * 64u);
                qf[2 * kb][0] = d0; qf[2 * kb][1] = d1;
                qf[2 * kb + 1][0] = d2; qf[2 * kb + 1][1] = d3;
            }
            // --- mma1: S chunk = K(16 rows) x Q(8 j's) over hd=64
            float c0 = 0.f, c1 = 0.f, c2 = 0.f, c3 = 0.f;
            #pragma unroll
            for (int ks = 0; ks < 8; ks++)
                mma8(c0, c1, c2, c3, ak[ks][0], ak[ks][1], ak[ks][2], ak[ks][3],
                     qf[ks][0], qf[ks][1]);
            // --- softmax numerator (no max-sub; scores are small)
            float p0 = exp2f(c0 * C1);
            float p1 = exp2f(c1 * C1);
            float p2 = exp2f(c2 * C1);
            float p3 = exp2f(c3 * C1);
            l0 += p0 + p1;
            l1 += p2 + p3;
            // --- re-fragment P via smem (per-warp private rows)
            unsigned* pb = &Ps[nt & 1][0];
            uint2 u0 = { f2tf32(p0), f2tf32(p1) };
            uint2 u1 = { f2tf32(p2), f2tf32(p3) };
            *(uint2*)&pb[(w * 16 + g) * 12 + 2 * tig] = u0;
            *(uint2*)&pb[(w * 16 + g + 8) * 12 + 2 * tig] = u1;
            __syncwarp();
            unsigned a0 = pb[(w * 16 + g) * 12 + tig];
            unsigned a1 = pb[(w * 16 + g + 8) * 12 + tig];
            unsigned a2 = pb[(w * 16 + g) * 12 + tig + 4];
            unsigned a3 = pb[(w * 16 + g + 8) * 12 + tig + 4];
            // --- mma2: O += P(16x8) x V(8 j's x 64 d)
            const int vr0 = (nt * 8 + tig) * QST;
            const int vr1 = (nt * 8 + tig + 4) * QST;
            #pragma unroll
            for (int dt = 0; dt < 8; dt++) {
                unsigned b0 = Vb[vr0 + dt * 8 + g];
                unsigned b1 = Vb[vr1 + dt * 8 + g];
                mma8(o[dt][0], o[dt][1], o[dt][2], o[dt][3], a0, a1, a2, a3, b0, b1);
            }
        }
        __syncthreads();
    }

    // Reduce l across the 4 lanes sharing a row, normalize, write out
    l0 += __shfl_xor_sync(0xffffffff, l0, 1);
    l0 += __shfl_xor_sync(0xffffffff, l0, 2);
    l1 += __shfl_xor_sync(0xffffffff, l1, 1);
    l1 += __shfl_xor_sync(0xffffffff, l1, 2);
    const float inv0 = 1.f / l0;
    const float inv1 = 1.f / l1;

    const int bb = bh >> 4;
    const int h  = bh & (H - 1);
    const int r0 = i0 + w * 16 + g;
    float* d0 = g_attn + ((size_t)(bb * S + r0)) * D + h * HD;
    float* d1 = g_attn + ((size_t)(bb * S + r0 + 8)) * D + h * HD;
    #pragma unroll
    for (int dt = 0; dt < 8; dt++) {
        float2 v0 = { rnd_tf32(o[dt][0] * inv0), rnd_tf32(o[dt][1] * inv0) };
        float2 v1 = { rnd_tf32(o[dt][2] * inv1), rnd_tf32(o[dt][3] * inv1) };
        *(float2*)&d0[dt * 8 + 2 * tig] = v0;
        *(float2*)&d1[dt * 8 + 2 * tig] = v1;
    }
}

// ---------------------------------------------------------------------------
extern "C" void kernel_launch(void* const* d_in, const int* in_sizes, int n_in,
                              void* d_out, int out_size)
{
    const float* x     = (const float*)d_in[0];
    const float* qkv_w = (const float*)d_in[1];
    const float* qkv_b = (const float*)d_in[2];
    const float* out_w = (const float*)d_in[3];
    const float* out_b = (const float*)d_in[4];
    float* out = (float*)d_out;

    constexpr int GEMM_SMEM = 2 * 2 * 128 * 36 * 4;   // 73728
    constexpr int ATTN_SMEM = 2 * 2 * 64 * 68 * 4;    // 69632
    cudaFuncSetAttribute(gemm_mma<true>,  cudaFuncAttributeMaxDynamicSharedMemorySize, GEMM_SMEM);
    cudaFuncSetAttribute(gemm_mma<false>, cudaFuncAttributeMaxDynamicSharedMemorySize, GEMM_SMEM);
    cudaFuncSetAttribute(flash_attn_mma,  cudaFuncAttributeMaxDynamicSharedMemorySize, ATTN_SMEM);

    // 0) Pre-round x and weights to tf32 so GEMMs can cp.async raw bits
    round_pre<<<2048, 256>>>(x, qkv_w, out_w);

    // 1) QKV projection (tf32 mma, cp.async pipeline), scatter to Q/K/V
    gemm_mma<true><<<dim3(N_QKV / 128, BS / 128), 256, GEMM_SMEM>>>(qkv_b, nullptr);

    // 2) Attention (quirk: K is the query side), tf32 mma + cp.async pipeline
    flash_attn_mma<<<dim3(B * H, S / 128), 256, ATTN_SMEM>>>();

    // 3) Output projection
    gemm_mma<false><<<dim3(D / 128, BS / 128), 256, GEMM_SMEM>>>(out_b, out);
}

// round 10
// speedup vs baseline: 1.2920x; 1.0915x over previous
#include <cuda_runtime.h>
#include <math.h>

// Problem constants
constexpr int B  = 2;
constexpr int S  = 2048;
constexpr int D  = 1024;
constexpr int H  = 16;
constexpr int HD = 64;
constexpr int BS = B * S;          // 4096 rows
constexpr int N_QKV = 3 * D;       // 3072

// Scratch (device globals — no allocation allowed)
__device__ float g_Q[B * H * S * HD];     // [b,h,s,hd]   (tf32-pre-rounded)
__device__ float g_K[B * H * S * HD];     // [b,h,s,hd]   (tf32-pre-rounded)
__device__ float g_V[B * H * S * HD];     // [b,h,hd,s]   TRANSPOSED (tf32-pre-rounded)
__device__ float g_attn[BS * D];          // [b,s,d]      (tf32-pre-rounded)
__device__ float g_xr[BS * D];            // x rounded to tf32
__device__ float g_wqkv[N_QKV * D];       // qkv_w rounded to tf32
__device__ float g_wout[D * D];           // out_w rounded to tf32

// ---------------------------------------------------------------------------
// Helpers
// ---------------------------------------------------------------------------
__device__ __forceinline__ unsigned f2tf32(float f) {
    unsigned u;
    asm("cvt.rna.tf32.f32 %0, %1;" : "=r"(u) : "f"(f));
    return u;
}
__device__ __forceinline__ float rnd_tf32(float f) {
    return __uint_as_float(f2tf32(f));
}
__device__ __forceinline__ unsigned smem_u32(const void* p) {
    unsigned a;
    asm("{ .reg .u64 t; cvta.to.shared.u64 t, %1; cvt.u32.u64 %0, t; }"
        : "=r"(a) : "l"(p));
    return a;
}
#define CP_ASYNC16(dst, src) \
    asm volatile("cp.async.cg.shared.global [%0], [%1], 16;" :: "r"(dst), "l"(src))
#define CP_COMMIT() asm volatile("cp.async.commit_group;")

// ldmatrix x4: each lane supplies the smem address of one 16B row.
__device__ __forceinline__ void ldsm4(unsigned& d0, unsigned& d1,
                                      unsigned& d2, unsigned& d3, unsigned addr) {
    asm volatile("ldmatrix.sync.aligned.m8n8.x4.shared.b16 {%0,%1,%2,%3}, [%4];"
        : "=r"(d0), "=r"(d1), "=r"(d2), "=r"(d3) : "r"(addr));
}

// D += A * B  (m16n8k8, A row-major, B col-major, tf32 in, fp32 accum)
__device__ __forceinline__ void mma8(float& d0, float& d1, float& d2, float& d3,
                                     unsigned a0, unsigned a1, unsigned a2, unsigned a3,
                                     unsigned b0, unsigned b1) {
    asm volatile(
        "mma.sync.aligned.m16n8k8.row.col.f32.tf32.tf32.f32 "
        "{%0,%1,%2,%3}, {%4,%5,%6,%7}, {%8,%9}, {%0,%1,%2,%3};"
        : "+f"(d0), "+f"(d1), "+f"(d2), "+f"(d3)
        : "r"(a0), "r"(a1), "r"(a2), "r"(a3), "r"(b0), "r"(b1));
}

// ---------------------------------------------------------------------------
// Pre-round pass: x, qkv_w, out_w -> tf32 (rna) copies, so GEMMs can cp.async
// raw bits with numerics identical to explicit conversion.
// ---------------------------------------------------------------------------
__global__ __launch_bounds__(256) void round_pre(
    const float* __restrict__ x,
    const float* __restrict__ wqkv,
    const float* __restrict__ wout)
{
    const int NX = BS * D / 4, NW = N_QKV * D / 4, NO = D * D / 4;
    const int total = NX + NW + NO;
    for (int idx = blockIdx.x * blockDim.x + threadIdx.x; idx < total;
         idx += gridDim.x * blockDim.x) {
        const float4* src;
        float4* dst;
        int off;
        if (idx < NX)            { src = (const float4*)x;    dst = (float4*)g_xr;   off = idx; }
        else if (idx < NX + NW)  { src = (const float4*)wqkv; dst = (float4*)g_wqkv; off = idx - NX; }
        else                     { src = (const float4*)wout; dst = (float4*)g_wout; off = idx - NX - NW; }
        float4 v = src[off];
        v.x = rnd_tf32(v.x); v.y = rnd_tf32(v.y);
        v.z = rnd_tf32(v.z); v.w = rnd_tf32(v.w);
        dst[off] = v;
    }
}

// ---------------------------------------------------------------------------
// TF32 tensor-core GEMM, 2-stage cp.async pipeline, ldmatrix fragment loads.
// C[m,n] = sum_k A[m,k] * W[n,k] + bias[n]
// BM=BN=128, BK=32, 256 threads = 8 warps (4 M x 2 N), warp tile 32x64.
// V is scattered TRANSPOSED ([b,h,hd,s]) so attention can ldmatrix it.
// Dynamic smem: 2 * 2 * 128*36 * 4 = 73728 bytes.
// ---------------------------------------------------------------------------
template <bool SCATTER>
__global__ __launch_bounds__(256) void gemm_mma(
    const float* __restrict__ bias,
    float* __restrict__ C)
{
    constexpr int AST = 36, TILE = 128 * AST;
    extern __shared__ unsigned smg[];
    unsigned* As = smg;               // [2][TILE]
    unsigned* Bs = smg + 2 * TILE;    // [2][TILE]
    const unsigned sA = smem_u32(As);
    const unsigned sB = smem_u32(Bs);

    const float* Ap = SCATTER ? g_xr   : g_attn;
    const float* Wp = SCATTER ? g_wqkv : g_wout;

    const int t    = threadIdx.x;
    const int lane = t & 31;
    const int w    = t >> 5;
    const int g    = lane >> 2;     // 0..7
    const int tig  = lane & 3;      // 0..3
    const int wm   = w & 3;         // 0..3
    const int wn   = w >> 2;        // 0..1
    const int m0   = blockIdx.y * 128;
    const int n0   = blockIdx.x * 128;

    // LDSM per-lane row/col map (element units within a tile)
    const int a_row = wm * 32 + ((lane >> 3) & 1) * 8 + (lane & 7);
    const int a_col = (lane >> 4) * 4;
    const unsigned aoff = (unsigned)(a_row * AST + a_col) * 4u;
    const int b_row = wn * 64 + ((lane >> 4) & 1) * 8 + (lane & 7);
    const int b_col = ((lane >> 3) & 1) * 4;
    const unsigned boff = (unsigned)(b_row * AST + b_col) * 4u;

    float acc[2][8][4];
    #pragma unroll
    for (int tm = 0; tm < 2; tm++)
        #pragma unroll
        for (int nt = 0; nt < 8; nt++)
            #pragma unroll
            for (int q = 0; q < 4; q++) acc[tm][nt][q] = 0.f;

    // Per-thread copy map: 4 x 16B per tile per stage
    const int id_row[4] = { (t + 0)   >> 3, (t + 256) >> 3,
                            (t + 512) >> 3, (t + 768) >> 3 };
    const int id_c4 = (t & 7) * 4;

    auto issue = [&](int k0, int buf) {
        #pragma unroll
        for (int r = 0; r < 4; r++) {
            const int row = id_row[r];
            const unsigned soff = (unsigned)(buf * TILE + row * AST + id_c4) * 4u;
            CP_ASYNC16(sA + soff, &Ap[(size_t)(m0 + row) * D + k0 + id_c4]);
            CP_ASYNC16(sB + soff, &Wp[(size_t)(n0 + row) * D + k0 + id_c4]);
        }
        CP_COMMIT();
    };

    constexpr int NK = D / 32;      // 32 k-chunks
    issue(0, 0);
    for (int i = 0; i < NK; i++) {
        if (i + 1 < NK) {
            issue((i + 1) * 32, (i + 1) & 1);
            asm volatile("cp.async.wait_group 1;");
        } else {
            asm volatile("cp.async.wait_group 0;");
        }
        __syncthreads();

        const unsigned Ab = sA + (unsigned)((i & 1) * TILE) * 4u;
        const unsigned Bb = sB + (unsigned)((i & 1) * TILE) * 4u;
        #pragma unroll
        for (int ks = 0; ks < 4; ks++) {
            unsigned af[2][4];
            ldsm4(af[0][0], af[0][1], af[0][2], af[0][3], Ab + aoff + ks * 32u);
            ldsm4(af[1][0], af[1][1], af[1][2], af[1][3],
                  Ab + aoff + 16u * AST * 4u + ks * 32u);
            unsigned bf[8][2];
            #pragma unroll
            for (int np = 0; np < 4; np++) {
                unsigned d0, d1, d2, d3;
                ldsm4(d0, d1, d2, d3, Bb + boff + (unsigned)(np * 16 * AST) * 4u + ks * 32u);
                bf[np * 2][0] = d0; bf[np * 2][1] = d1;
                bf[np * 2 + 1][0] = d2; bf[np * 2 + 1][1] = d3;
            }
            #pragma unroll
            for (int tm = 0; tm < 2; tm++)
                #pragma unroll
                for (int nt = 0; nt < 8; nt++)
                    mma8(acc[tm][nt][0], acc[tm][nt][1], acc[tm][nt][2], acc[tm][nt][3],
                         af[tm][0], af[tm][1], af[tm][2], af[tm][3],
                         bf[nt][0], bf[nt][1]);
        }
        __syncthreads();
    }

    // Epilogue: C frag rows (g, g+8), cols (2tig, 2tig+1)
    #pragma unroll
    for (int tm = 0; tm < 2; tm++) {
        const int r0 = m0 + wm * 32 + tm * 16 + g;
        #pragma unroll
        for (int nt = 0; nt < 8; nt++) {
            const int c = n0 + wn * 64 + nt * 8 + 2 * tig;
            const float b0 = bias[c], b1 = bias[c + 1];
            float2 v0 = { acc[tm][nt][0] + b0, acc[tm][nt][1] + b1 };
            float2 v1 = { acc[tm][nt][2] + b0, acc[tm][nt][3] + b1 };
            if (SCATTER) {
                v0.x = rnd_tf32(v0.x); v0.y = rnd_tf32(v0.y);
                v1.x = rnd_tf32(v1.x); v1.y = rnd_tf32(v1.y);
                const int which = c >> 10;          // 0=Q,1=K,2=V
                const int dd = c & (D - 1);
                const int h  = dd >> 6;
                const int hi = dd & (HD - 1);       // even
                const int bb0 = r0 >> 11, ss0 = r0 & (S - 1);
                const int bb1 = (r0 + 8) >> 11, ss1 = (r0 + 8) & (S - 1);
                if (which == 2) {
                    // V stored transposed: [b,h,hd,s]
                    float* dv = g_V + ((size_t)(bb0 * H + h) * HD) * S;
                    dv[(size_t)hi * S + ss0]       = v0.x;
                    dv[(size_t)(hi + 1) * S + ss0] = v0.y;
                    float* dv1 = g_V + ((size_t)(bb1 * H + h) * HD) * S;
                    dv1[(size_t)hi * S + ss1]       = v1.x;
                    dv1[(size_t)(hi + 1) * S + ss1] = v1.y;
                } else {
                    float* dst = (which == 0) ? g_Q : g_K;
                    *(float2*)&dst[(((size_t)(bb0 * H + h) * S) + ss0) * HD + hi] = v0;
                    *(float2*)&dst[(((size_t)(bb1 * H + h) * S) + ss1) * HD + hi] = v1;
                }
            } else {
                *(float2*)&C[(size_t)r0 * D + c] = v0;
                *(float2*)&C[(size_t)(r0 + 8) * D + c] = v1;
            }
        }
    }
}

// ---------------------------------------------------------------------------
// TF32 tensor-core attention (quirk: scores[i,j] = k_i . q_j, scale 1/8),
// 2-stage cp.async pipeline; ldmatrix for BOTH Q and V fragments
// (V is pre-transposed in gmem: [b,h,hd,s]).
// CTA: 128 i-rows (K side), 8 warps x 16 rows.
// No max subtraction (scores are tiny): l += e^{s/8}, O += e^{s/8} V.
// Dynamic smem: 2 stages * (Q+VT) * 64*68 * 4 = 69632 bytes.
// ---------------------------------------------------------------------------
__global__ __launch_bounds__(256) void flash_attn_mma()
{
    constexpr int QST = 68, QTILE = 64 * QST;
    extern __shared__ unsigned smg[];
    unsigned* Qs = smg;               // [2][QTILE]
    unsigned* Vs = smg + 2 * QTILE;   // [2][QTILE]  (VT: row=hd, col=j)
    __shared__ unsigned Ps[2][128 * 12];
    const unsigned sQ = smem_u32(Qs);
    const unsigned sV = smem_u32(Vs);

    const int bh = blockIdx.x;                 // b*H + h
    const int i0 = blockIdx.y * 128;
    const int t    = threadIdx.x;
    const int lane = t & 31;
    const int w    = t >> 5;
    const int g    = lane >> 2;
    const int tig  = lane & 3;

    const float* Kp = g_K + (size_t)bh * S * HD;
    const float* Qp = g_Q + (size_t)bh * S * HD;
    const float* Vp = g_V + (size_t)bh * HD * S;   // transposed layout

    // Q LDSM map: per nt, x4 over 16 k: m0 rows nt*8+0..7 @k+0, m1 @+4, m2 @+8, m3 @+12
    const unsigned qoff = (unsigned)((lane & 7) * QST + (lane >> 3) * 4) * 4u;
    // V LDSM map (VT rows = hd): m0 rows p*16+0..7 @j+0, m1 @j+4, m2 rows +8 @j+0, m3 @j+4
    const unsigned voff = (unsigned)(((lane & 7) + ((lane >> 4) & 1) * 8) * QST
                                     + ((lane >> 3) & 1) * 4) * 4u;

    // K A-fragments (g_K is tf32-pre-rounded: raw bits are the tf32 operands)
    unsigned ak[8][4];
    {
        const int kr = i0 + w * 16 + g;
        #pragma unroll
        for (int ks = 0; ks < 8; ks++) {
            ak[ks][0] = __float_as_uint(Kp[(size_t)kr * HD + ks * 8 + tig]);
            ak[ks][1] = __float_as_uint(Kp[(size_t)(kr + 8) * HD + ks * 8 + tig]);
            ak[ks][2] = __float_as_uint(Kp[(size_t)kr * HD + ks * 8 + tig + 4]);
            ak[ks][3] = __float_as_uint(Kp[(size_t)(kr + 8) * HD + ks * 8 + tig + 4]);
        }
    }

    float o[8][4];
    #pragma unroll
    for (int dt = 0; dt < 8; dt++)
        #pragma unroll
        for (int q = 0; q < 4; q++) o[dt][q] = 0.f;
    float l0 = 0.f, l1 = 0.f;
    const float C1 = 0.18033688011112042f;     // log2(e)/8

    const int jrow = t >> 2;                   // copy map: 0..63
    const int jc4  = (t & 3) * 4;              // covers 16 of 64 cols
    auto issue = [&](int j0, int buf) {
        #pragma unroll
        for (int r = 0; r < 4; r++) {
            const int c4 = jc4 + r * 16;
            const unsigned soff = (unsigned)(buf * QTILE + jrow * QST + c4) * 4u;
            CP_ASYNC16(sQ + soff, &Qp[(size_t)(j0 + jrow) * HD + c4]);
            // VT: row jrow is hd index, columns are j (contiguous in s)
            CP_ASYNC16(sV + soff, &Vp[(size_t)jrow * S + j0 + c4]);
        }
        CP_COMMIT();
    };

    constexpr int NJ = S / 64;   // 32 tiles
    issue(0, 0);
    for (int i = 0; i < NJ; i++) {
        if (i + 1 < NJ) {
            issue((i + 1) * 64, (i + 1) & 1);
            asm volatile("cp.async.wait_group 1;");
        } else {
            asm volatile("cp.async.wait_group 0;");
        }
        __syncthreads();

        const unsigned Qbb = sQ + (unsigned)((i & 1) * QTILE) * 4u;
        const unsigned Vbb = sV + (unsigned)((i & 1) * QTILE) * 4u;

        #pragma unroll
        for (int nt = 0; nt < 8; nt++) {
            // --- Q fragments via ldmatrix: 4 x ldsm4 cover ks=0..7
            unsigned qf[8][2];
            #pragma unroll
            for (int kb = 0; kb < 4; kb++) {
                unsigned d0, d1, d2, d3;
                ldsm4(d0, d1, d2, d3,
                      Qbb + qoff + (unsigned)(nt * 8 * QST) * 4u + (unsigned)kb * 64u);
                qf[2 * kb][0] = d0; qf[2 * kb][1] = d1;
                qf[2 * kb + 1][0] = d2; qf[2 * kb + 1][1] = d3;
            }
            // --- mma1: S chunk = K(16 rows) x Q(8 j's) over hd=64
            float c0 = 0.f, c1 = 0.f, c2 = 0.f, c3 = 0.f;
            #pragma unroll
            for (int ks = 0; ks < 8; ks++)
                mma8(c0, c1, c2, c3, ak[ks][0], ak[ks][1], ak[ks][2], ak[ks][3],
                     qf[ks][0], qf[ks][1]);
            // --- softmax numerator (no max-sub; scores are small)
            float p0 = exp2f(c0 * C1);
            float p1 = exp2f(c1 * C1);
            float p2 = exp2f(c2 * C1);
            float p3 = exp2f(c3 * C1);
            l0 += p0 + p1;
            l1 += p2 + p3;
            // --- re-fragment P via smem (per-warp private rows)
            unsigned* pb = &Ps[nt & 1][0];
            uint2 u0 = { f2tf32(p0), f2tf32(p1) };
            uint2 u1 = { f2tf32(p2), f2tf32(p3) };
            *(uint2*)&pb[(w * 16 + g) * 12 + 2 * tig] = u0;
            *(uint2*)&pb[(w * 16 + g + 8) * 12 + 2 * tig] = u1;
            __syncwarp();
            unsigned a0 = pb[(w * 16 + g) * 12 + tig];
            unsigned a1 = pb[(w * 16 + g + 8) * 12 + tig];
            unsigned a2 = pb[(w * 16 + g) * 12 + tig + 4];
            unsigned a3 = pb[(w * 16 + g + 8) * 12 + tig + 4];
            // --- V fragments via ldmatrix on VT (rows = hd, k = j)
            unsigned vf[8][2];
            #pragma unroll
            for (int p = 0; p < 4; p++) {
                unsigned d0, d1, d2, d3;
                ldsm4(d0, d1, d2, d3,
                      Vbb + voff + (unsigned)(p * 16 * QST) * 4u + (unsigned)(nt * 8) * 4u);
                vf[2 * p][0] = d0;     vf[2 * p][1] = d1;
                vf[2 * p + 1][0] = d2; vf[2 * p + 1][1] = d3;
            }
            // --- mma2: O += P(16x8) x V(8 j's x 64 d)
            #pragma unroll
            for (int dt = 0; dt < 8; dt++)
                mma8(o[dt][0], o[dt][1], o[dt][2], o[dt][3], a0, a1, a2, a3,
                     vf[dt][0], vf[dt][1]);
        }
        __syncthreads();
    }

    // Reduce l across the 4 lanes sharing a row, normalize, write out
    l0 += __shfl_xor_sync(0xffffffff, l0, 1);
    l0 += __shfl_xor_sync(0xffffffff, l0, 2);
    l1 += __shfl_xor_sync(0xffffffff, l1, 1);
    l1 += __shfl_xor_sync(0xffffffff, l1, 2);
    const float inv0 = 1.f / l0;
    const float inv1 = 1.f / l1;

    const int bb = bh >> 4;
    const int h  = bh & (H - 1);
    const int r0 = i0 + w * 16 + g;
    float* d0 = g_attn + ((size_t)(bb * S + r0)) * D + h * HD;
    float* d1 = g_attn + ((size_t)(bb * S + r0 + 8)) * D + h * HD;
    #pragma unroll
    for (int dt = 0; dt < 8; dt++) {
        float2 v0 = { rnd_tf32(o[dt][0] * inv0), rnd_tf32(o[dt][1] * inv0) };
        float2 v1 = { rnd_tf32(o[dt][2] * inv1), rnd_tf32(o[dt][3] * inv1) };
        *(float2*)&d0[dt * 8 + 2 * tig] = v0;
        *(float2*)&d1[dt * 8 + 2 * tig] = v1;
    }
}

// ---------------------------------------------------------------------------
extern "C" void kernel_launch(void* const* d_in, const int* in_sizes, int n_in,
                              void* d_out, int out_size)
{
    const float* x     = (const float*)d_in[0];
    const float* qkv_w = (const float*)d_in[1];
    const float* qkv_b = (const float*)d_in[2];
    const float* out_w = (const float*)d_in[3];
    const float* out_b = (const float*)d_in[4];
    float* out = (float*)d_out;

    constexpr int GEMM_SMEM = 2 * 2 * 128 * 36 * 4;   // 73728
    constexpr int ATTN_SMEM = 2 * 2 * 64 * 68 * 4;    // 69632
    cudaFuncSetAttribute(gemm_mma<true>,  cudaFuncAttributeMaxDynamicSharedMemorySize, GEMM_SMEM);
    cudaFuncSetAttribute(gemm_mma<false>, cudaFuncAttributeMaxDynamicSharedMemorySize, GEMM_SMEM);
    cudaFuncSetAttribute(flash_attn_mma,  cudaFuncAttributeMaxDynamicSharedMemorySize, ATTN_SMEM);

    // 0) Pre-round x and weights to tf32 so GEMMs can cp.async raw bits
    round_pre<<<2048, 256>>>(x, qkv_w, out_w);

    // 1) QKV projection (tf32 mma, cp.async pipeline), scatter to Q/K/VT
    gemm_mma<true><<<dim3(N_QKV / 128, BS / 128), 256, GEMM_SMEM>>>(qkv_b, nullptr);

    // 2) Attention (quirk: K is the query side), tf32 mma + cp.async pipeline
    flash_attn_mma<<<dim3(B * H, S / 128), 256, ATTN_SMEM>>>();

    // 3) Output projection
    gemm_mma<false><<<dim3(D / 128, BS / 128), 256, GEMM_SMEM>>>(out_b, out);
}